// round 12
// baseline (speedup 1.0000x reference)
#include <cuda_runtime.h>
#include <cuda_fp16.h>

#define B 8
#define S 512
#define E 64
#define H 8

// ---- dynamic smem layout (bytes) ------------------------------------------
// K storage: 4 head-pair regions; half2 = (head hp, head hp+4).
// Within a region: 256 blocks of 2 keys; block = 64B data padded to 80B
// (stride 20 words -> g-lanes 0..7 hit distinct bank quads).
// offset(kb2, d, rin) = kb2*80 + d*8 + rin*4   (d=0..7 dim, rin=0..1 key)
#define HPS      20496                 // 256*80 + 16 pad (heads -> distinct quads)
#define KS_BYTES (4 * HPS)             // 81984
#define WS_OFF   KS_BYTES
#define WS_ROW   65                    // pad-65: scalar LDS banks (e+k)%32
#define WS_BYTES (64 * WS_ROW * 4)     // 16640
#define CS_OFF   (WS_OFF + WS_BYTES)
#define CS_ROW   68
#define CS_BYTES (16 * CS_ROW * 4)     // 4352
#define BS_OFF   (CS_OFF + CS_BYTES)
#define SMEM_TOTAL (BS_OFF + 256)      // 103232 -> 2 blocks/SM

__device__ __forceinline__ unsigned h2u(__half2 h) { return *reinterpret_cast<unsigned*>(&h); }
__device__ __forceinline__ __half2 u2h(unsigned u) { return *reinterpret_cast<__half2*>(&u); }

__device__ __forceinline__ __half2 h2ex2(__half2 v) {
    unsigned r, a = h2u(v);
    asm("ex2.approx.f16x2 %0, %1;" : "=r"(r) : "r"(a));
    return u2h(r);
}

// ---------------------------------------------------------------------------
// One kernel: block = (b, 16-query chunk). 256 blocks x 512 threads.
// Phase A: build fp16 K, head-PAIR packed (half2 = heads h and h+4).
// Phase B: attention; thread = (head pair, query, key-split g). One ex2 per
//          key serves BOTH heads; no cross-half reduction needed.
// Phase C: in-block projection (pad-65 scalar W, conflict-free).
// ---------------------------------------------------------------------------
__global__ void __launch_bounds__(512, 2) fused_kernel(
    const float* __restrict__ x,      // [B, S, E]
    const float* __restrict__ theta,  // [8]
    const float* __restrict__ W,      // [64, 64] (e, k)
    const float* __restrict__ bo,     // [64]
    float* __restrict__ out)          // [B*S, 64]
{
    extern __shared__ char sm[];
    float* Ws = (float*)(sm + WS_OFF);
    float* Cs = (float*)(sm + CS_OFF);
    float* bs = (float*)(sm + BS_OFF);

    const int tid   = threadIdx.x;    // 0..511
    const int bid   = blockIdx.x;     // 0..255
    const int b     = bid >> 5;
    const int chunk = bid & 31;       // 16-query chunk

    // ---- stage W (pad-65 scalar) + bias ----
    for (int i = tid; i < 64 * 64; i += 512) {
        int e = i >> 6, k = i & 63;
        Ws[e * WS_ROW + k] = __ldg(W + i);
    }
    if (tid < 64) bs[tid] = __ldg(bo + tid);

    float th[8];
#pragma unroll
    for (int j = 0; j < 8; ++j) th[j] = __ldg(theta + j);

    // ---- Phase A: build fp16 K, head-pair packed ----
    // item m -> key r = m>>4, c = m&15: head = c>>1, half hi = c&1.
    // After computing this (head, hi) 4-dim group, exchange with lane^8
    // (head+4, same hi) and lanes c<8 store the packed half2s.
    const float4* x4 = (const float4*)x + (size_t)b * (S * E / 4);
#pragma unroll
    for (int j = 0; j < 16; ++j) {
        int m = j * 512 + tid;
        int r = m >> 4;               // key row 0..511
        int c = m & 15;
        float4 v = __ldg(x4 + m);
        int tb = (c & 1) * 4;
        float f0 = __cosf(v.x + th[tb + 0]);
        float f1 = __cosf(v.y + th[tb + 1]);
        float f2 = __cosf(v.z + th[tb + 2]);
        float f3 = __cosf(v.w + th[tb + 3]);
        float g0 = __shfl_xor_sync(0xffffffffu, f0, 1);
        float g1 = __shfl_xor_sync(0xffffffffu, f1, 1);
        float g2 = __shfl_xor_sync(0xffffffffu, f2, 1);
        float g3 = __shfl_xor_sync(0xffffffffu, f3, 1);
        bool hi = (c & 1);
        float c0 = hi ? g0 : f0, c1 = hi ? g1 : f1;
        float c2 = hi ? g2 : f2, c3 = hi ? g3 : f3;
        float c4 = hi ? f0 : g0, c5 = hi ? f1 : g1;
        float c6 = hi ? f2 : g2, c7 = hi ? f3 : g3;
        float q1 = c0 * c1, q2 = q1 * c2, q3 = q2 * c3;
        float q4 = q3 * c4, q5 = q4 * c5, q6 = q5 * c6, q7 = q6 * c7;
        float t01 = c1 * c2, t23 = c3 * c4, t45 = c5 * c6;
        float q0 = t01 * t23 * t45 * c7;
        float a0 = hi ? q4 : q0, a1 = hi ? q5 : q1;
        float a2 = hi ? q6 : q2, a3 = hi ? q7 : q3;
        // partner = lane^8 -> same r, same hi, head+4
        float p0 = __shfl_xor_sync(0xffffffffu, a0, 8);
        float p1 = __shfl_xor_sync(0xffffffffu, a1, 8);
        float p2 = __shfl_xor_sync(0xffffffffu, a2, 8);
        float p3 = __shfl_xor_sync(0xffffffffu, a3, 8);
        if ((c & 8) == 0) {
            int hp = c >> 1;          // 0..3
            char* dst = sm + hp * HPS + (r >> 1) * 80 + (r & 1) * 4 + tb * 8;
            *(__half2*)(dst + 0)  = __floats2half2_rn(a0, p0);
            *(__half2*)(dst + 8)  = __floats2half2_rn(a1, p1);
            *(__half2*)(dst + 16) = __floats2half2_rn(a2, p2);
            *(__half2*)(dst + 24) = __floats2half2_rn(a3, p3);
        }
    }
    __syncthreads();

    // ---- Phase B: attention ----
    // tid = hp*128 + qq*8 + g : head pair hp, query qq (0..15), g (0..7).
    const int hp = tid >> 7;
    const int rr = tid & 127;
    const int qq = rr >> 3;
    const int g  = rr & 7;
    const int sq = chunk * 16 + qq;   // query's key-row index

    __half2 q2[8];
    {
        const char* qp = sm + hp * HPS + (sq >> 1) * 80 + (sq & 1) * 4;
        const __half2 sch = __float2half2_rn(0.51010202f); // (1/sqrt(8))*log2(e)
#pragma unroll
        for (int d = 0; d < 8; ++d)
            q2[d] = __hmul2(*(const __half2*)(qp + d * 8), sch);
    }

    float F[16];
#pragma unroll
    for (int d = 0; d < 16; ++d) F[d] = 0.f;
    float lfA = 0.f, lfB = 0.f;

    const __half2 hz = __float2half2_rn(0.f);
    const char* base = sm + hp * HPS + g * 80;   // kb2 = 8*t + g

    for (int o = 0; o < 4; ++o) {
        __half2 acc[8];
#pragma unroll
        for (int d = 0; d < 8; ++d) acc[d] = hz;
        __half2 l2 = hz;
        const char* po = base + o * (8 * 640);
#pragma unroll
        for (int u = 0; u < 8; ++u) {
            const char* p = po + u * 640;
            uint4 va = *(const uint4*)(p);        // d0,d1 x rin0,rin1
            uint4 vb = *(const uint4*)(p + 16);   // d2,d3
            uint4 vc = *(const uint4*)(p + 32);   // d4,d5
            uint4 vd = *(const uint4*)(p + 48);   // d6,d7
            // --- rin 0: components .x (even d), .z (odd d) ---
            {
                __half2 k0 = u2h(va.x), k1 = u2h(va.z), k2 = u2h(vb.x), k3 = u2h(vb.z);
                __half2 k4 = u2h(vc.x), k5 = u2h(vc.z), k6 = u2h(vd.x), k7 = u2h(vd.z);
                __half2 sA = __hmul2(q2[0], k0);
                sA = __hfma2(q2[1], k1, sA);
                sA = __hfma2(q2[2], k2, sA);
                sA = __hfma2(q2[3], k3, sA);
                __half2 sB = __hmul2(q2[4], k4);
                sB = __hfma2(q2[5], k5, sB);
                sB = __hfma2(q2[6], k6, sB);
                sB = __hfma2(q2[7], k7, sB);
                __half2 w2 = h2ex2(__hadd2(sA, sB));   // both heads' weights
                l2 = __hadd2(l2, w2);
                acc[0] = __hfma2(w2, k0, acc[0]);
                acc[1] = __hfma2(w2, k1, acc[1]);
                acc[2] = __hfma2(w2, k2, acc[2]);
                acc[3] = __hfma2(w2, k3, acc[3]);
                acc[4] = __hfma2(w2, k4, acc[4]);
                acc[5] = __hfma2(w2, k5, acc[5]);
                acc[6] = __hfma2(w2, k6, acc[6]);
                acc[7] = __hfma2(w2, k7, acc[7]);
            }
            // --- rin 1: components .y, .w ---
            {
                __half2 k0 = u2h(va.y), k1 = u2h(va.w), k2 = u2h(vb.y), k3 = u2h(vb.w);
                __half2 k4 = u2h(vc.y), k5 = u2h(vc.w), k6 = u2h(vd.y), k7 = u2h(vd.w);
                __half2 sA = __hmul2(q2[0], k0);
                sA = __hfma2(q2[1], k1, sA);
                sA = __hfma2(q2[2], k2, sA);
                sA = __hfma2(q2[3], k3, sA);
                __half2 sB = __hmul2(q2[4], k4);
                sB = __hfma2(q2[5], k5, sB);
                sB = __hfma2(q2[6], k6, sB);
                sB = __hfma2(q2[7], k7, sB);
                __half2 w2 = h2ex2(__hadd2(sA, sB));
                l2 = __hadd2(l2, w2);
                acc[0] = __hfma2(w2, k0, acc[0]);
                acc[1] = __hfma2(w2, k1, acc[1]);
                acc[2] = __hfma2(w2, k2, acc[2]);
                acc[3] = __hfma2(w2, k3, acc[3]);
                acc[4] = __hfma2(w2, k4, acc[4]);
                acc[5] = __hfma2(w2, k5, acc[5]);
                acc[6] = __hfma2(w2, k6, acc[6]);
                acc[7] = __hfma2(w2, k7, acc[7]);
            }
        }
        // promote this 16-key chunk to fp32 (low = head hp, high = head hp+4)
#pragma unroll
        for (int d = 0; d < 8; ++d) {
            float2 t = __half22float2(acc[d]);
            F[d]     += t.x;
            F[8 + d] += t.y;
        }
        float2 tl = __half22float2(l2);
        lfA += tl.x;
        lfB += tl.y;
    }

    // reduce across the 8 g-lanes (contiguous within the warp)
    float red[18];
#pragma unroll
    for (int d = 0; d < 16; ++d) red[d] = F[d];
    red[16] = lfA;
    red[17] = lfB;
#pragma unroll
    for (int v = 0; v < 18; ++v) {
        red[v] += __shfl_xor_sync(0xffffffffu, red[v], 1);
        red[v] += __shfl_xor_sync(0xffffffffu, red[v], 2);
        red[v] += __shfl_xor_sync(0xffffffffu, red[v], 4);
    }

    if (g == 0) {
        float invA = 1.f / red[16];
        float invB = 1.f / red[17];
        float* cpA = Cs + qq * CS_ROW + hp * 8;
        *(float4*)(cpA + 0) = make_float4(red[0] * invA, red[1] * invA, red[2] * invA, red[3] * invA);
        *(float4*)(cpA + 4) = make_float4(red[4] * invA, red[5] * invA, red[6] * invA, red[7] * invA);
        float* cpB = Cs + qq * CS_ROW + (hp + 4) * 8;
        *(float4*)(cpB + 0) = make_float4(red[8] * invB, red[9] * invB, red[10] * invB, red[11] * invB);
        *(float4*)(cpB + 4) = make_float4(red[12] * invB, red[13] * invB, red[14] * invB, red[15] * invB);
    }
    __syncthreads();

    // ---- Phase C: projection. out[n,e] = sum_k ctx[n,k]*W[e,k] + b[e] ----
    {
        const int q2i  = tid >> 5;        // 0..15
        const int lane = tid & 31;
        const float* crow = Cs + q2i * CS_ROW;
        float acc0 = bs[lane];
        float acc1 = bs[lane + 32];
#pragma unroll 8
        for (int k = 0; k < 64; ++k) {
            float c = crow[k];                         // broadcast
            acc0 = fmaf(c, Ws[lane * WS_ROW + k], acc0);
            acc1 = fmaf(c, Ws[(lane + 32) * WS_ROW + k], acc1);
        }
        const int n = b * S + chunk * 16 + q2i;
        out[(size_t)n * 64 + lane]      = acc0;
        out[(size_t)n * 64 + lane + 32] = acc1;
    }
}

extern "C" void kernel_launch(void* const* d_in, const int* in_sizes, int n_in,
                              void* d_out, int out_size)
{
    const float* x     = (const float*)d_in[0];  // [8, 512, 64]
    const float* theta = (const float*)d_in[1];  // [8]
    const float* W_o   = (const float*)d_in[2];  // [64, 64]
    const float* b_o   = (const float*)d_in[3];  // [64]
    float* out = (float*)d_out;

    cudaFuncSetAttribute(fused_kernel,
                         cudaFuncAttributeMaxDynamicSharedMemorySize, SMEM_TOTAL);
    fused_kernel<<<256, 512, SMEM_TOTAL>>>(x, theta, W_o, b_o, out);
}